// round 12
// baseline (speedup 1.0000x reference)
#include <cuda_runtime.h>
#include <cuda_fp16.h>
#include <math.h>
#include <stdint.h>

// ---------------------------------------------------------------------------
// LayerNorm LSTM cell, B=4096, I=H=1024.
// GEMMs via mma.sync fp16 (HMMA): CTA 128x128, warp 64x32, K-chunk 64,
// 3-stage cp.async, 2 CTAs/SM, double-buffered register fragments.
// Convert split into 5 launches so ncu (-s 5 -c 1) captures gemm/epilogue.
// ---------------------------------------------------------------------------

#define B_DIM   4096
#define H_DIM   1024
#define FH_DIM  4096
#define K_DIM   1024
#define LN_EPS  1e-5f
#define FGBIAS  (-1.0f)

// ---------------------------- scratch --------------------------------------
__device__ __half g_xh[2][(size_t)B_DIM * K_DIM];   // inputs / hx (fp16)
__device__ __half g_wh[2][(size_t)FH_DIM * K_DIM];  // w_i2h / w_h2h (fp16)
__device__ __half g_i2h[(size_t)B_DIM * FH_DIM];    // fp16 intermediates
__device__ __half g_h2h[(size_t)B_DIM * FH_DIM];

// ---------------------------- asm helpers ----------------------------------
__device__ __forceinline__ uint32_t smem_u32(const void* p) {
    uint32_t a;
    asm("{ .reg .u64 t; cvta.to.shared.u64 t, %1; cvt.u32.u64 %0, t; }" : "=r"(a) : "l"(p));
    return a;
}

#define CP_ASYNC16(saddr, gptr) \
    asm volatile("cp.async.cg.shared.global [%0], [%1], 16;" :: "r"(saddr), "l"(gptr))
#define CP_COMMIT() asm volatile("cp.async.commit_group;")
#define CP_WAIT(n)  asm volatile("cp.async.wait_group %0;" :: "n"(n))

#define LDSM4(r, addr) \
    asm volatile("ldmatrix.sync.aligned.m8n8.x4.shared.b16 {%0,%1,%2,%3}, [%4];" \
        : "=r"((r)[0]), "=r"((r)[1]), "=r"((r)[2]), "=r"((r)[3]) : "r"(addr))

#define MMA16816(d, a, b) \
    asm volatile("mma.sync.aligned.m16n8k16.row.col.f32.f16.f16.f32 " \
        "{%0,%1,%2,%3}, {%4,%5,%6,%7}, {%8,%9}, {%0,%1,%2,%3};" \
        : "+f"((d)[0]), "+f"((d)[1]), "+f"((d)[2]), "+f"((d)[3]) \
        : "r"((a)[0]), "r"((a)[1]), "r"((a)[2]), "r"((a)[3]), \
          "r"((b)[0]), "r"((b)[1]))

// ---------------------- conversion kernel ----------------------------------
// mat: 0=inputs, 1=hx, 2=w_i2h rows [0,2048), 3=w_i2h rows [2048,4096), 4=w_h2h
__global__ __launch_bounds__(256)
void convert_fp16(const float* __restrict__ inputs, const float* __restrict__ hx,
                  const float* __restrict__ w0, const float* __restrict__ w1,
                  int mat)
{
    const float* src;
    __half* dst;
    size_t off = 0;
    switch (mat) {
        case 0:  src = inputs; dst = g_xh[0]; break;
        case 1:  src = hx;     dst = g_xh[1]; break;
        case 2:  src = w0;     dst = g_wh[0]; break;
        case 3:  src = w0;     dst = g_wh[0]; off = (size_t)1024 * 256; break;
        default: src = w1;     dst = g_wh[1]; break;
    }
    size_t idx = (size_t)blockIdx.x * 256 + threadIdx.x + off;  // one 8-float chunk
    const float4* s4 = reinterpret_cast<const float4*>(src + idx * 8);
    float4 v0 = s4[0], v1 = s4[1];
    float av[8] = { v0.x, v0.y, v0.z, v0.w, v1.x, v1.y, v1.z, v1.w };

    union { __half b[8]; uint4 u; } Hh;
#pragma unroll
    for (int i = 0; i < 8; i++) Hh.b[i] = __float2half_rn(av[i]);

    *reinterpret_cast<uint4*>(dst + idx * 8) = Hh.u;
}

// ------------------------------ HMMA GEMM ----------------------------------
#define KCH       64
#define NSTAGE    3
#define TILE_B    16384                   // 128 rows * 128 B
#define STAGE_B   (2 * TILE_B)            // A, W
#define GEMM_SMEM (NSTAGE * STAGE_B)      // 98304
#define NKC       (K_DIM / KCH)           // 16

__global__ __launch_bounds__(256, 2)
void gemm_tc(const float* __restrict__ bias0, const float* __restrict__ bias1)
{
    extern __shared__ char smem[];
    const uint32_t sbase = smem_u32(smem);
    const int tid = threadIdx.x, wid = tid >> 5, lane = tid & 31;
    const int bx = blockIdx.x, by = blockIdx.y, which = blockIdx.z;

    const __half* srcA = g_xh[which] + (size_t)(by * 128) * K_DIM;
    const __half* srcW = g_wh[which] + (size_t)(bx * 128) * K_DIM;

    auto issue_stage = [&](int ks, int st) {
        const uint32_t sdst = sbase + st * STAGE_B;
#pragma unroll
        for (int j = 0; j < 8; j++) {
            int idx = tid + 256 * j;              // 0..2047 (16B chunks)
            int isW = (idx >= 1024);
            int w   = idx & 1023;
            int row = w >> 3, c = w & 7;
            const __half* gb = isW ? srcW : srcA;
            const __half* g = gb + (size_t)row * K_DIM + ks * KCH + c * 8;
            uint32_t s = sdst + isW * TILE_B + row * 128 + ((c ^ (row & 7)) << 4);
            CP_ASYNC16(s, g);
        }
        CP_COMMIT();
    };

    issue_stage(0, 0);
    issue_stage(1, 1);

    const int wm = wid & 1;            // 2 m-halves of 64
    const int wn = wid >> 1;           // 4 n-quarters of 32

    float acc[4][4][4];
#pragma unroll
    for (int mi = 0; mi < 4; mi++)
#pragma unroll
        for (int ni = 0; ni < 4; ni++)
#pragma unroll
            for (int q = 0; q < 4; q++) acc[mi][ni][q] = 0.f;

    const int a_r = (lane & 15);
    const int a_cc = lane >> 4;
    const int b_r = ((lane >> 4) << 3) + (lane & 7);
    const int b_cc = (lane >> 3) & 1;

    // double-buffered fragments
    uint32_t af[2][4][4], bh[2][4][2];

    auto load_frags = [&](int buf, uint32_t base, int kt) {
#pragma unroll
        for (int g = 0; g < 2; g++) {
            int r = wn * 32 + g * 16 + b_r;
            int c = 2 * kt + b_cc;
            uint32_t addr = base + TILE_B + r * 128 + ((c ^ (r & 7)) << 4);
            uint32_t t[4];
            LDSM4(t, addr);
            bh[buf][2 * g + 0][0] = t[0]; bh[buf][2 * g + 0][1] = t[1];
            bh[buf][2 * g + 1][0] = t[2]; bh[buf][2 * g + 1][1] = t[3];
        }
#pragma unroll
        for (int mi = 0; mi < 4; mi++) {
            int r = wm * 64 + mi * 16 + a_r;
            int c = 2 * kt + a_cc;
            uint32_t addr = base + r * 128 + ((c ^ (r & 7)) << 4);
            LDSM4(af[buf][mi], addr);
        }
    };

    auto consume_stage = [&](uint32_t base) {
        load_frags(0, base, 0);
#pragma unroll
        for (int kt = 0; kt < 4; kt++) {
            const int cb = kt & 1;
            if (kt < 3) load_frags(cb ^ 1, base, kt + 1);
#pragma unroll
            for (int mi = 0; mi < 4; mi++)
#pragma unroll
                for (int ni = 0; ni < 4; ni++)
                    MMA16816(acc[mi][ni], af[cb][mi], bh[cb][ni]);
        }
    };

    for (int kc = 0; kc < NKC - 2; kc++) {
        const int st = kc % NSTAGE;
        __syncthreads();                       // all reads of stage (kc-1)%3 done
        issue_stage(kc + 2, (kc + 2) % NSTAGE);
        CP_WAIT(2);                            // stage kc landed
        __syncthreads();
        consume_stage(sbase + st * STAGE_B);
    }
    // kc = NKC-2: in flight {NKC-2, NKC-1}
    __syncthreads();
    CP_WAIT(1);
    __syncthreads();
    consume_stage(sbase + ((NKC - 2) % NSTAGE) * STAGE_B);
    // kc = NKC-1: in flight {NKC-1}
    __syncthreads();
    CP_WAIT(0);
    __syncthreads();
    consume_stage(sbase + ((NKC - 1) % NSTAGE) * STAGE_B);

    // ---- epilogue: bias + store fp16 ----
    const float* bias = which ? bias1 : bias0;
    __half* C = which ? g_h2h : g_i2h;
    const int mrow0 = by * 128 + wm * 64;
    const int ncol0 = bx * 128 + wn * 32;
#pragma unroll
    for (int mi = 0; mi < 4; mi++) {
        const int r0 = mrow0 + mi * 16 + (lane >> 2);
#pragma unroll
        for (int ni = 0; ni < 4; ni++) {
            const int cc = ncol0 + ni * 8 + (lane & 3) * 2;
            const float b0 = __ldg(bias + cc), b1 = __ldg(bias + cc + 1);
            __half2 v0 = __floats2half2_rn(acc[mi][ni][0] + b0, acc[mi][ni][1] + b1);
            __half2 v1 = __floats2half2_rn(acc[mi][ni][2] + b0, acc[mi][ni][3] + b1);
            *reinterpret_cast<__half2*>(C + (size_t)r0 * FH_DIM + cc) = v0;
            *reinterpret_cast<__half2*>(C + (size_t)(r0 + 8) * FH_DIM + cc) = v1;
        }
    }
}

// --------------------------- fused LN/gate epilogue ------------------------
__device__ __forceinline__ float warp_sum(float v) {
#pragma unroll
    for (int o = 16; o; o >>= 1) v += __shfl_down_sync(0xffffffffu, v, o);
    return v;
}
// fast sigmoid/tanh via __expf (rel err ~2^-21, safe at all arguments)
__device__ __forceinline__ float fast_sigmoid(float x) {
    float e = __expf(-x);
    return __fdividef(1.0f, 1.0f + e);
}
__device__ __forceinline__ float fast_tanh(float x) {
    float e = __expf(-2.0f * fabsf(x));
    float r = __fdividef(1.0f - e, 1.0f + e);
    return copysignf(r, x);
}

__global__ __launch_bounds__(256)
void lstm_epilogue(const float* __restrict__ cx,
                   const float* __restrict__ w1, const float* __restrict__ b1,
                   const float* __restrict__ w2, const float* __restrict__ b2,
                   const float* __restrict__ w3, const float* __restrict__ b3,
                   float* __restrict__ hx_new,
                   float* __restrict__ cx_new)
{
    const int r   = blockIdx.x;
    const int tid = threadIdx.x;
    const int lane = tid & 31;
    const int wrp  = tid >> 5;

    const uint4* __restrict__ ri4 =
        reinterpret_cast<const uint4*>(g_i2h + (size_t)r * FH_DIM);
    const uint4* __restrict__ rh4 =
        reinterpret_cast<const uint4*>(g_h2h + (size_t)r * FH_DIM);

    __shared__ __half s_i[FH_DIM];
    __shared__ __half s_h[FH_DIM];
    __shared__ float sc[4][8];
    uint4* s_i4 = reinterpret_cast<uint4*>(s_i);
    uint4* s_h4 = reinterpret_cast<uint4*>(s_h);

    // prefetch cx row + h-position LN params (hidden behind pass-1 reduction)
    float cxv[4], pw1[4], pb1[4], pw2[4], pb2[4], pw3[4], pb3[4];
#pragma unroll
    for (int u = 0; u < 4; u++) {
        const int h = tid + u * 256;
        cxv[u] = cx[(size_t)r * H_DIM + h];
        pw1[u] = w1[h]; pb1[u] = b1[h];
        pw2[u] = w2[h]; pb2[u] = b2[h];
        pw3[u] = w3[h]; pb3[u] = b3[h];
    }

    float s1 = 0.f, q1 = 0.f, s2 = 0.f, q2 = 0.f;
#pragma unroll
    for (int u = 0; u < 2; u++) {
        int j = tid + u * 256;                 // uint4 (8-half) index 0..511
        union { uint4 u4; __half2 h2[4]; } A, Bv;
        A.u4 = ri4[j]; Bv.u4 = rh4[j];
        s_i4[j] = A.u4; s_h4[j] = Bv.u4;
#pragma unroll
        for (int p = 0; p < 4; p++) {
            float2 t = __half22float2(A.h2[p]);
            s1 += t.x + t.y; q1 += t.x * t.x + t.y * t.y;
            t = __half22float2(Bv.h2[p]);
            s2 += t.x + t.y; q2 += t.x * t.x + t.y * t.y;
        }
    }
    s1 = warp_sum(s1); q1 = warp_sum(q1);
    s2 = warp_sum(s2); q2 = warp_sum(q2);
    if (lane == 0) { sc[0][wrp] = s1; sc[1][wrp] = q1; sc[2][wrp] = s2; sc[3][wrp] = q2; }
    __syncthreads();
    if (wrp < 4 && lane < 8) {                 // warp-parallel combine
        float v = sc[wrp][lane];
        v += __shfl_down_sync(0xffu, v, 4);
        v += __shfl_down_sync(0xffu, v, 2);
        v += __shfl_down_sync(0xffu, v, 1);
        if (lane == 0) sc[wrp][0] = v;
    }
    __syncthreads();
    s1 = sc[0][0]; q1 = sc[1][0]; s2 = sc[2][0]; q2 = sc[3][0];

    const float inv_n = 1.0f / (float)FH_DIM;
    const float m1 = s1 * inv_n;
    const float m2 = s2 * inv_n;
    float var1 = fmaxf((q1 - s1 * m1) / (float)(FH_DIM - 1), 0.f);
    float var2 = fmaxf((q2 - s2 * m2) / (float)(FH_DIM - 1), 0.f);
    const float d1 = 1.0f / (sqrtf(var1) + LN_EPS);
    const float d2 = 1.0f / (sqrtf(var2) + LN_EPS);

    float c_reg[4], o_reg[4];
    float s3 = 0.f, q3 = 0.f;
#pragma unroll
    for (int u = 0; u < 4; u++) {
        const int h = tid + u * 256;
        const int jf = h + H_DIM, jo = h + 2 * H_DIM, jc = h + 3 * H_DIM;

        float xi = fmaf((__half2float(s_i[h]) - m1) * d1, pw1[u], pb1[u])
                 + fmaf((__half2float(s_h[h]) - m2) * d2, pw2[u], pb2[u]);
        float xf = fmaf((__half2float(s_i[jf]) - m1) * d1, w1[jf], b1[jf])
                 + fmaf((__half2float(s_h[jf]) - m2) * d2, w2[jf], b2[jf]);
        float xo = fmaf((__half2float(s_i[jo]) - m1) * d1, w1[jo], b1[jo])
                 + fmaf((__half2float(s_h[jo]) - m2) * d2, w2[jo], b2[jo]);
        float xc = fmaf((__half2float(s_i[jc]) - m1) * d1, w1[jc], b1[jc])
                 + fmaf((__half2float(s_h[jc]) - m2) * d2, w2[jc], b2[jc]);

        float ig = fast_sigmoid(xi);
        float fg = fast_sigmoid(xf + FGBIAS);
        float og = fast_sigmoid(xo);
        float ct = fast_tanh(xc);

        float c = fg * cxv[u] + ig * ct;
        c_reg[u] = c;
        o_reg[u] = og;
        s3 += c; q3 += c * c;
        cx_new[(size_t)r * H_DIM + h] = c;
    }

    __syncthreads();
    s3 = warp_sum(s3); q3 = warp_sum(q3);
    if (lane == 0) { sc[0][wrp] = s3; sc[1][wrp] = q3; }
    __syncthreads();
    if (wrp < 2 && lane < 8) {
        float v = sc[wrp][lane];
        v += __shfl_down_sync(0xffu, v, 4);
        v += __shfl_down_sync(0xffu, v, 2);
        v += __shfl_down_sync(0xffu, v, 1);
        if (lane == 0) sc[wrp][0] = v;
    }
    __syncthreads();
    s3 = sc[0][0]; q3 = sc[1][0];

    const float m3 = s3 / (float)H_DIM;
    float var3 = fmaxf((q3 - s3 * m3) / (float)(H_DIM - 1), 0.f);
    const float d3 = 1.0f / (sqrtf(var3) + LN_EPS);

#pragma unroll
    for (int u = 0; u < 4; u++) {
        const int h = tid + u * 256;
        float ln = fmaf((c_reg[u] - m3) * d3, pw3[u], pb3[u]);
        hx_new[(size_t)r * H_DIM + h] = o_reg[u] * fast_tanh(ln);
    }
}

// ------------------------------- launcher ----------------------------------
extern "C" void kernel_launch(void* const* d_in, const int* in_sizes, int n_in,
                              void* d_out, int out_size)
{
    const float* inputs   = (const float*)d_in[0];
    const float* hx       = (const float*)d_in[1];
    const float* cx       = (const float*)d_in[2];
    const float* w_i2h    = (const float*)d_in[3];
    const float* b_i2h    = (const float*)d_in[4];
    const float* w_h2h    = (const float*)d_in[5];
    const float* b_h2h    = (const float*)d_in[6];
    const float* ln_i2h_w = (const float*)d_in[7];
    const float* ln_i2h_b = (const float*)d_in[8];
    const float* ln_h2h_w = (const float*)d_in[9];
    const float* ln_h2h_b = (const float*)d_in[10];
    const float* ln_h2o_w = (const float*)d_in[11];
    const float* ln_h2o_b = (const float*)d_in[12];

    float* out    = (float*)d_out;
    float* hx_new = out;
    float* cx_new = out + (size_t)B_DIM * H_DIM;

    cudaFuncSetAttribute(gemm_tc, cudaFuncAttributeMaxDynamicSharedMemorySize, GEMM_SMEM);

    // 5 convert launches (profiling alignment: gemm_tc becomes launch #6)
    convert_fp16<<<2048, 256>>>(inputs, hx, w_i2h, w_h2h, 0);
    convert_fp16<<<2048, 256>>>(inputs, hx, w_i2h, w_h2h, 1);
    convert_fp16<<<1024, 256>>>(inputs, hx, w_i2h, w_h2h, 2);
    convert_fp16<<<1024, 256>>>(inputs, hx, w_i2h, w_h2h, 3);
    convert_fp16<<<2048, 256>>>(inputs, hx, w_i2h, w_h2h, 4);

    gemm_tc<<<dim3(FH_DIM / 128, B_DIM / 128, 2), 256, GEMM_SMEM>>>(b_i2h, b_h2h);

    lstm_epilogue<<<B_DIM, 256>>>(cx,
                                  ln_i2h_w, ln_i2h_b,
                                  ln_h2h_w, ln_h2h_b,
                                  ln_h2o_w, ln_h2o_b,
                                  hx_new, cx_new);
}

// round 13
// speedup vs baseline: 1.0802x; 1.0802x over previous
#include <cuda_runtime.h>
#include <cuda_fp16.h>
#include <math.h>
#include <stdint.h>

// ---------------------------------------------------------------------------
// LayerNorm LSTM cell, B=4096, I=H=1024.
// GEMMs via mma.sync fp16 (HMMA): CTA 128x128, warp 64x32, K-chunk 64,
// 3-stage cp.async, 2 CTAs/SM, double-buffered register fragments (R11 GEMM).
// Convert: single merged launch, 64B/thread (MLP=4).
// ---------------------------------------------------------------------------

#define B_DIM   4096
#define H_DIM   1024
#define FH_DIM  4096
#define K_DIM   1024
#define LN_EPS  1e-5f
#define FGBIAS  (-1.0f)

// ---------------------------- scratch --------------------------------------
__device__ __half g_xh[2][(size_t)B_DIM * K_DIM];   // inputs / hx (fp16)
__device__ __half g_wh[2][(size_t)FH_DIM * K_DIM];  // w_i2h / w_h2h (fp16)
__device__ __half g_i2h[(size_t)B_DIM * FH_DIM];    // fp16 intermediates
__device__ __half g_h2h[(size_t)B_DIM * FH_DIM];

// ---------------------------- asm helpers ----------------------------------
__device__ __forceinline__ uint32_t smem_u32(const void* p) {
    uint32_t a;
    asm("{ .reg .u64 t; cvta.to.shared.u64 t, %1; cvt.u32.u64 %0, t; }" : "=r"(a) : "l"(p));
    return a;
}

#define CP_ASYNC16(saddr, gptr) \
    asm volatile("cp.async.cg.shared.global [%0], [%1], 16;" :: "r"(saddr), "l"(gptr))
#define CP_COMMIT() asm volatile("cp.async.commit_group;")
#define CP_WAIT(n)  asm volatile("cp.async.wait_group %0;" :: "n"(n))

#define LDSM4(r, addr) \
    asm volatile("ldmatrix.sync.aligned.m8n8.x4.shared.b16 {%0,%1,%2,%3}, [%4];" \
        : "=r"((r)[0]), "=r"((r)[1]), "=r"((r)[2]), "=r"((r)[3]) : "r"(addr))

#define MMA16816(d, a, b) \
    asm volatile("mma.sync.aligned.m16n8k16.row.col.f32.f16.f16.f32 " \
        "{%0,%1,%2,%3}, {%4,%5,%6,%7}, {%8,%9}, {%0,%1,%2,%3};" \
        : "+f"((d)[0]), "+f"((d)[1]), "+f"((d)[2]), "+f"((d)[3]) \
        : "r"((a)[0]), "r"((a)[1]), "r"((a)[2]), "r"((a)[3]), \
          "r"((b)[0]), "r"((b)[1]))

// ---------------------- conversion kernel ----------------------------------
// grid: (1024, 4). Each thread converts 16 floats (4 independent LDG.128).
__global__ __launch_bounds__(256)
void convert_fp16(const float* __restrict__ inputs, const float* __restrict__ hx,
                  const float* __restrict__ w0, const float* __restrict__ w1)
{
    const int mat = blockIdx.y;
    const float* src;
    switch (mat) {
        case 0:  src = inputs; break;
        case 1:  src = hx;     break;
        case 2:  src = w0;     break;
        default: src = w1;     break;
    }
    size_t idx = (size_t)blockIdx.x * 256 + threadIdx.x;   // one 16-float chunk
    const float4* s4 = reinterpret_cast<const float4*>(src + idx * 16);
    float4 v0 = s4[0], v1 = s4[1], v2 = s4[2], v3 = s4[3];
    float av[16] = { v0.x, v0.y, v0.z, v0.w, v1.x, v1.y, v1.z, v1.w,
                     v2.x, v2.y, v2.z, v2.w, v3.x, v3.y, v3.z, v3.w };

    union { __half b[16]; uint4 u[2]; } Hh;
#pragma unroll
    for (int i = 0; i < 16; i++) Hh.b[i] = __float2half_rn(av[i]);

    __half* hp = (mat < 2) ? g_xh[mat] : g_wh[mat - 2];
    uint4* d = reinterpret_cast<uint4*>(hp + idx * 16);
    d[0] = Hh.u[0];
    d[1] = Hh.u[1];
}

// ------------------------------ HMMA GEMM ----------------------------------
#define KCH       64
#define NSTAGE    3
#define TILE_B    16384                   // 128 rows * 128 B
#define STAGE_B   (2 * TILE_B)            // A, W
#define GEMM_SMEM (NSTAGE * STAGE_B)      // 98304
#define NKC       (K_DIM / KCH)           // 16

__global__ __launch_bounds__(256, 2)
void gemm_tc(const float* __restrict__ bias0, const float* __restrict__ bias1)
{
    extern __shared__ char smem[];
    const uint32_t sbase = smem_u32(smem);
    const int tid = threadIdx.x, wid = tid >> 5, lane = tid & 31;
    const int bx = blockIdx.x, by = blockIdx.y, which = blockIdx.z;

    const __half* srcA = g_xh[which] + (size_t)(by * 128) * K_DIM;
    const __half* srcW = g_wh[which] + (size_t)(bx * 128) * K_DIM;

    auto issue_stage = [&](int ks, int st) {
        const uint32_t sdst = sbase + st * STAGE_B;
#pragma unroll
        for (int j = 0; j < 8; j++) {
            int idx = tid + 256 * j;              // 0..2047 (16B chunks)
            int isW = (idx >= 1024);
            int w   = idx & 1023;
            int row = w >> 3, c = w & 7;
            const __half* gb = isW ? srcW : srcA;
            const __half* g = gb + (size_t)row * K_DIM + ks * KCH + c * 8;
            uint32_t s = sdst + isW * TILE_B + row * 128 + ((c ^ (row & 7)) << 4);
            CP_ASYNC16(s, g);
        }
        CP_COMMIT();
    };

    issue_stage(0, 0);
    issue_stage(1, 1);

    const int wm = wid & 1;            // 2 m-halves of 64
    const int wn = wid >> 1;           // 4 n-quarters of 32

    float acc[4][4][4];
#pragma unroll
    for (int mi = 0; mi < 4; mi++)
#pragma unroll
        for (int ni = 0; ni < 4; ni++)
#pragma unroll
            for (int q = 0; q < 4; q++) acc[mi][ni][q] = 0.f;

    const int a_r = (lane & 15);
    const int a_cc = lane >> 4;
    const int b_r = ((lane >> 4) << 3) + (lane & 7);
    const int b_cc = (lane >> 3) & 1;

    // double-buffered fragments
    uint32_t af[2][4][4], bh[2][4][2];

    auto load_frags = [&](int buf, uint32_t base, int kt) {
#pragma unroll
        for (int g = 0; g < 2; g++) {
            int r = wn * 32 + g * 16 + b_r;
            int c = 2 * kt + b_cc;
            uint32_t addr = base + TILE_B + r * 128 + ((c ^ (r & 7)) << 4);
            uint32_t t[4];
            LDSM4(t, addr);
            bh[buf][2 * g + 0][0] = t[0]; bh[buf][2 * g + 0][1] = t[1];
            bh[buf][2 * g + 1][0] = t[2]; bh[buf][2 * g + 1][1] = t[3];
        }
#pragma unroll
        for (int mi = 0; mi < 4; mi++) {
            int r = wm * 64 + mi * 16 + a_r;
            int c = 2 * kt + a_cc;
            uint32_t addr = base + r * 128 + ((c ^ (r & 7)) << 4);
            LDSM4(af[buf][mi], addr);
        }
    };

    auto consume_stage = [&](uint32_t base) {
        load_frags(0, base, 0);
#pragma unroll
        for (int kt = 0; kt < 4; kt++) {
            const int cb = kt & 1;
            if (kt < 3) load_frags(cb ^ 1, base, kt + 1);
#pragma unroll
            for (int mi = 0; mi < 4; mi++)
#pragma unroll
                for (int ni = 0; ni < 4; ni++)
                    MMA16816(acc[mi][ni], af[cb][mi], bh[cb][ni]);
        }
    };

    for (int kc = 0; kc < NKC - 2; kc++) {
        const int st = kc % NSTAGE;
        __syncthreads();                       // all reads of stage (kc-1)%3 done
        issue_stage(kc + 2, (kc + 2) % NSTAGE);
        CP_WAIT(2);                            // stage kc landed
        __syncthreads();
        consume_stage(sbase + st * STAGE_B);
    }
    // kc = NKC-2: in flight {NKC-2, NKC-1}
    __syncthreads();
    CP_WAIT(1);
    __syncthreads();
    consume_stage(sbase + ((NKC - 2) % NSTAGE) * STAGE_B);
    // kc = NKC-1: in flight {NKC-1}
    __syncthreads();
    CP_WAIT(0);
    __syncthreads();
    consume_stage(sbase + ((NKC - 1) % NSTAGE) * STAGE_B);

    // ---- epilogue: bias + store fp16 ----
    const float* bias = which ? bias1 : bias0;
    __half* C = which ? g_h2h : g_i2h;
    const int mrow0 = by * 128 + wm * 64;
    const int ncol0 = bx * 128 + wn * 32;
#pragma unroll
    for (int mi = 0; mi < 4; mi++) {
        const int r0 = mrow0 + mi * 16 + (lane >> 2);
#pragma unroll
        for (int ni = 0; ni < 4; ni++) {
            const int cc = ncol0 + ni * 8 + (lane & 3) * 2;
            const float b0 = __ldg(bias + cc), b1 = __ldg(bias + cc + 1);
            __half2 v0 = __floats2half2_rn(acc[mi][ni][0] + b0, acc[mi][ni][1] + b1);
            __half2 v1 = __floats2half2_rn(acc[mi][ni][2] + b0, acc[mi][ni][3] + b1);
            *reinterpret_cast<__half2*>(C + (size_t)r0 * FH_DIM + cc) = v0;
            *reinterpret_cast<__half2*>(C + (size_t)(r0 + 8) * FH_DIM + cc) = v1;
        }
    }
}

// --------------------------- fused LN/gate epilogue ------------------------
__device__ __forceinline__ float warp_sum(float v) {
#pragma unroll
    for (int o = 16; o; o >>= 1) v += __shfl_down_sync(0xffffffffu, v, o);
    return v;
}
// fast sigmoid/tanh via __expf (rel err ~2^-21, safe at all arguments)
__device__ __forceinline__ float fast_sigmoid(float x) {
    float e = __expf(-x);
    return __fdividef(1.0f, 1.0f + e);
}
__device__ __forceinline__ float fast_tanh(float x) {
    float e = __expf(-2.0f * fabsf(x));
    float r = __fdividef(1.0f - e, 1.0f + e);
    return copysignf(r, x);
}

__global__ __launch_bounds__(256)
void lstm_epilogue(const float* __restrict__ cx,
                   const float* __restrict__ w1, const float* __restrict__ b1,
                   const float* __restrict__ w2, const float* __restrict__ b2,
                   const float* __restrict__ w3, const float* __restrict__ b3,
                   float* __restrict__ hx_new,
                   float* __restrict__ cx_new)
{
    const int r   = blockIdx.x;
    const int tid = threadIdx.x;
    const int lane = tid & 31;
    const int wrp  = tid >> 5;

    const uint4* __restrict__ ri4 =
        reinterpret_cast<const uint4*>(g_i2h + (size_t)r * FH_DIM);
    const uint4* __restrict__ rh4 =
        reinterpret_cast<const uint4*>(g_h2h + (size_t)r * FH_DIM);

    __shared__ __half s_i[FH_DIM];
    __shared__ __half s_h[FH_DIM];
    __shared__ float sc[4][8];
    uint4* s_i4 = reinterpret_cast<uint4*>(s_i);
    uint4* s_h4 = reinterpret_cast<uint4*>(s_h);

    // prefetch cx row + h-position LN params (hidden behind pass-1 reduction)
    float cxv[4], pw1[4], pb1[4], pw2[4], pb2[4], pw3[4], pb3[4];
#pragma unroll
    for (int u = 0; u < 4; u++) {
        const int h = tid + u * 256;
        cxv[u] = cx[(size_t)r * H_DIM + h];
        pw1[u] = w1[h]; pb1[u] = b1[h];
        pw2[u] = w2[h]; pb2[u] = b2[h];
        pw3[u] = w3[h]; pb3[u] = b3[h];
    }

    float s1 = 0.f, q1 = 0.f, s2 = 0.f, q2 = 0.f;
#pragma unroll
    for (int u = 0; u < 2; u++) {
        int j = tid + u * 256;                 // uint4 (8-half) index 0..511
        union { uint4 u4; __half2 h2[4]; } A, Bv;
        A.u4 = ri4[j]; Bv.u4 = rh4[j];
        s_i4[j] = A.u4; s_h4[j] = Bv.u4;
#pragma unroll
        for (int p = 0; p < 4; p++) {
            float2 t = __half22float2(A.h2[p]);
            s1 += t.x + t.y; q1 += t.x * t.x + t.y * t.y;
            t = __half22float2(Bv.h2[p]);
            s2 += t.x + t.y; q2 += t.x * t.x + t.y * t.y;
        }
    }
    s1 = warp_sum(s1); q1 = warp_sum(q1);
    s2 = warp_sum(s2); q2 = warp_sum(q2);
    if (lane == 0) { sc[0][wrp] = s1; sc[1][wrp] = q1; sc[2][wrp] = s2; sc[3][wrp] = q2; }
    __syncthreads();
    if (wrp < 4 && lane < 8) {                 // warp-parallel combine
        float v = sc[wrp][lane];
        v += __shfl_down_sync(0xffu, v, 4);
        v += __shfl_down_sync(0xffu, v, 2);
        v += __shfl_down_sync(0xffu, v, 1);
        if (lane == 0) sc[wrp][0] = v;
    }
    __syncthreads();
    s1 = sc[0][0]; q1 = sc[1][0]; s2 = sc[2][0]; q2 = sc[3][0];

    const float inv_n = 1.0f / (float)FH_DIM;
    const float m1 = s1 * inv_n;
    const float m2 = s2 * inv_n;
    float var1 = fmaxf((q1 - s1 * m1) / (float)(FH_DIM - 1), 0.f);
    float var2 = fmaxf((q2 - s2 * m2) / (float)(FH_DIM - 1), 0.f);
    const float d1 = 1.0f / (sqrtf(var1) + LN_EPS);
    const float d2 = 1.0f / (sqrtf(var2) + LN_EPS);

    float c_reg[4], o_reg[4];
    float s3 = 0.f, q3 = 0.f;
#pragma unroll
    for (int u = 0; u < 4; u++) {
        const int h = tid + u * 256;
        const int jf = h + H_DIM, jo = h + 2 * H_DIM, jc = h + 3 * H_DIM;

        float xi = fmaf((__half2float(s_i[h]) - m1) * d1, pw1[u], pb1[u])
                 + fmaf((__half2float(s_h[h]) - m2) * d2, pw2[u], pb2[u]);
        float xf = fmaf((__half2float(s_i[jf]) - m1) * d1, w1[jf], b1[jf])
                 + fmaf((__half2float(s_h[jf]) - m2) * d2, w2[jf], b2[jf]);
        float xo = fmaf((__half2float(s_i[jo]) - m1) * d1, w1[jo], b1[jo])
                 + fmaf((__half2float(s_h[jo]) - m2) * d2, w2[jo], b2[jo]);
        float xc = fmaf((__half2float(s_i[jc]) - m1) * d1, w1[jc], b1[jc])
                 + fmaf((__half2float(s_h[jc]) - m2) * d2, w2[jc], b2[jc]);

        float ig = fast_sigmoid(xi);
        float fg = fast_sigmoid(xf + FGBIAS);
        float og = fast_sigmoid(xo);
        float ct = fast_tanh(xc);

        float c = fg * cxv[u] + ig * ct;
        c_reg[u] = c;
        o_reg[u] = og;
        s3 += c; q3 += c * c;
        cx_new[(size_t)r * H_DIM + h] = c;
    }

    __syncthreads();
    s3 = warp_sum(s3); q3 = warp_sum(q3);
    if (lane == 0) { sc[0][wrp] = s3; sc[1][wrp] = q3; }
    __syncthreads();
    if (wrp < 2 && lane < 8) {
        float v = sc[wrp][lane];
        v += __shfl_down_sync(0xffu, v, 4);
        v += __shfl_down_sync(0xffu, v, 2);
        v += __shfl_down_sync(0xffu, v, 1);
        if (lane == 0) sc[wrp][0] = v;
    }
    __syncthreads();
    s3 = sc[0][0]; q3 = sc[1][0];

    const float m3 = s3 / (float)H_DIM;
    float var3 = fmaxf((q3 - s3 * m3) / (float)(H_DIM - 1), 0.f);
    const float d3 = 1.0f / (sqrtf(var3) + LN_EPS);

#pragma unroll
    for (int u = 0; u < 4; u++) {
        const int h = tid + u * 256;
        float ln = fmaf((c_reg[u] - m3) * d3, pw3[u], pb3[u]);
        hx_new[(size_t)r * H_DIM + h] = o_reg[u] * fast_tanh(ln);
    }
}

// ------------------------------- launcher ----------------------------------
extern "C" void kernel_launch(void* const* d_in, const int* in_sizes, int n_in,
                              void* d_out, int out_size)
{
    const float* inputs   = (const float*)d_in[0];
    const float* hx       = (const float*)d_in[1];
    const float* cx       = (const float*)d_in[2];
    const float* w_i2h    = (const float*)d_in[3];
    const float* b_i2h    = (const float*)d_in[4];
    const float* w_h2h    = (const float*)d_in[5];
    const float* b_h2h    = (const float*)d_in[6];
    const float* ln_i2h_w = (const float*)d_in[7];
    const float* ln_i2h_b = (const float*)d_in[8];
    const float* ln_h2h_w = (const float*)d_in[9];
    const float* ln_h2h_b = (const float*)d_in[10];
    const float* ln_h2o_w = (const float*)d_in[11];
    const float* ln_h2o_b = (const float*)d_in[12];

    float* out    = (float*)d_out;
    float* hx_new = out;
    float* cx_new = out + (size_t)B_DIM * H_DIM;

    cudaFuncSetAttribute(gemm_tc, cudaFuncAttributeMaxDynamicSharedMemorySize, GEMM_SMEM);

    convert_fp16<<<dim3(1024, 4), 256>>>(inputs, hx, w_i2h, w_h2h);

    gemm_tc<<<dim3(FH_DIM / 128, B_DIM / 128, 2), 256, GEMM_SMEM>>>(b_i2h, b_h2h);

    lstm_epilogue<<<B_DIM, 256>>>(cx,
                                  ln_i2h_w, ln_i2h_b,
                                  ln_h2h_w, ln_h2h_b,
                                  ln_h2o_w, ln_h2o_b,
                                  hx_new, cx_new);
}

// round 14
// speedup vs baseline: 1.0878x; 1.0071x over previous
#include <cuda_runtime.h>
#include <cuda_fp16.h>
#include <math.h>
#include <stdint.h>

// ---------------------------------------------------------------------------
// LayerNorm LSTM cell, B=4096, I=H=1024.
// GEMMs via mma.sync fp16 (HMMA): CTA 128x128, warp 64x32, K-chunk 64,
// 3-stage cp.async, 2 CTAs/SM, double-buffered register fragments.
// Convert: single merged launch, 32B/thread (R11 config, measured best).
// Epilogue: LN-param/cx register prefetch (R13 gain).
// ---------------------------------------------------------------------------

#define B_DIM   4096
#define H_DIM   1024
#define FH_DIM  4096
#define K_DIM   1024
#define LN_EPS  1e-5f
#define FGBIAS  (-1.0f)

// ---------------------------- scratch --------------------------------------
__device__ __half g_xh[2][(size_t)B_DIM * K_DIM];   // inputs / hx (fp16)
__device__ __half g_wh[2][(size_t)FH_DIM * K_DIM];  // w_i2h / w_h2h (fp16)
__device__ __half g_i2h[(size_t)B_DIM * FH_DIM];    // fp16 intermediates
__device__ __half g_h2h[(size_t)B_DIM * FH_DIM];

// ---------------------------- asm helpers ----------------------------------
__device__ __forceinline__ uint32_t smem_u32(const void* p) {
    uint32_t a;
    asm("{ .reg .u64 t; cvta.to.shared.u64 t, %1; cvt.u32.u64 %0, t; }" : "=r"(a) : "l"(p));
    return a;
}

#define CP_ASYNC16(saddr, gptr) \
    asm volatile("cp.async.cg.shared.global [%0], [%1], 16;" :: "r"(saddr), "l"(gptr))
#define CP_COMMIT() asm volatile("cp.async.commit_group;")
#define CP_WAIT(n)  asm volatile("cp.async.wait_group %0;" :: "n"(n))

#define LDSM4(r, addr) \
    asm volatile("ldmatrix.sync.aligned.m8n8.x4.shared.b16 {%0,%1,%2,%3}, [%4];" \
        : "=r"((r)[0]), "=r"((r)[1]), "=r"((r)[2]), "=r"((r)[3]) : "r"(addr))

#define MMA16816(d, a, b) \
    asm volatile("mma.sync.aligned.m16n8k16.row.col.f32.f16.f16.f32 " \
        "{%0,%1,%2,%3}, {%4,%5,%6,%7}, {%8,%9}, {%0,%1,%2,%3};" \
        : "+f"((d)[0]), "+f"((d)[1]), "+f"((d)[2]), "+f"((d)[3]) \
        : "r"((a)[0]), "r"((a)[1]), "r"((a)[2]), "r"((a)[3]), \
          "r"((b)[0]), "r"((b)[1]))

// ---------------------- conversion kernel ----------------------------------
// grid: (2048, 4). Each thread converts 8 floats (2 LDG.128 -> 1 STG.128).
__global__ __launch_bounds__(256)
void convert_fp16(const float* __restrict__ inputs, const float* __restrict__ hx,
                  const float* __restrict__ w0, const float* __restrict__ w1)
{
    const int mat = blockIdx.y;
    const float* src;
    switch (mat) {
        case 0:  src = inputs; break;
        case 1:  src = hx;     break;
        case 2:  src = w0;     break;
        default: src = w1;     break;
    }
    size_t idx = (size_t)blockIdx.x * 256 + threadIdx.x;   // one 8-float chunk
    const float4* s4 = reinterpret_cast<const float4*>(src + idx * 8);
    float4 v0 = s4[0], v1 = s4[1];
    float av[8] = { v0.x, v0.y, v0.z, v0.w, v1.x, v1.y, v1.z, v1.w };

    union { __half b[8]; uint4 u; } Hh;
#pragma unroll
    for (int i = 0; i < 8; i++) Hh.b[i] = __float2half_rn(av[i]);

    __half* hp = (mat < 2) ? g_xh[mat] : g_wh[mat - 2];
    *reinterpret_cast<uint4*>(hp + idx * 8) = Hh.u;
}

// ------------------------------ HMMA GEMM ----------------------------------
#define KCH       64
#define NSTAGE    3
#define TILE_B    16384                   // 128 rows * 128 B
#define STAGE_B   (2 * TILE_B)            // A, W
#define GEMM_SMEM (NSTAGE * STAGE_B)      // 98304
#define NKC       (K_DIM / KCH)           // 16

__global__ __launch_bounds__(256, 2)
void gemm_tc(const float* __restrict__ bias0, const float* __restrict__ bias1)
{
    extern __shared__ char smem[];
    const uint32_t sbase = smem_u32(smem);
    const int tid = threadIdx.x, wid = tid >> 5, lane = tid & 31;
    const int bx = blockIdx.x, by = blockIdx.y, which = blockIdx.z;

    const __half* srcA = g_xh[which] + (size_t)(by * 128) * K_DIM;
    const __half* srcW = g_wh[which] + (size_t)(bx * 128) * K_DIM;

    auto issue_stage = [&](int ks, int st) {
        const uint32_t sdst = sbase + st * STAGE_B;
#pragma unroll
        for (int j = 0; j < 8; j++) {
            int idx = tid + 256 * j;              // 0..2047 (16B chunks)
            int isW = (idx >= 1024);
            int w   = idx & 1023;
            int row = w >> 3, c = w & 7;
            const __half* gb = isW ? srcW : srcA;
            const __half* g = gb + (size_t)row * K_DIM + ks * KCH + c * 8;
            uint32_t s = sdst + isW * TILE_B + row * 128 + ((c ^ (row & 7)) << 4);
            CP_ASYNC16(s, g);
        }
        CP_COMMIT();
    };

    issue_stage(0, 0);
    issue_stage(1, 1);

    const int wm = wid & 1;            // 2 m-halves of 64
    const int wn = wid >> 1;           // 4 n-quarters of 32

    float acc[4][4][4];
#pragma unroll
    for (int mi = 0; mi < 4; mi++)
#pragma unroll
        for (int ni = 0; ni < 4; ni++)
#pragma unroll
            for (int q = 0; q < 4; q++) acc[mi][ni][q] = 0.f;

    const int a_r = (lane & 15);
    const int a_cc = lane >> 4;
    const int b_r = ((lane >> 4) << 3) + (lane & 7);
    const int b_cc = (lane >> 3) & 1;

    // double-buffered fragments
    uint32_t af[2][4][4], bh[2][4][2];

    auto load_frags = [&](int buf, uint32_t base, int kt) {
#pragma unroll
        for (int g = 0; g < 2; g++) {
            int r = wn * 32 + g * 16 + b_r;
            int c = 2 * kt + b_cc;
            uint32_t addr = base + TILE_B + r * 128 + ((c ^ (r & 7)) << 4);
            uint32_t t[4];
            LDSM4(t, addr);
            bh[buf][2 * g + 0][0] = t[0]; bh[buf][2 * g + 0][1] = t[1];
            bh[buf][2 * g + 1][0] = t[2]; bh[buf][2 * g + 1][1] = t[3];
        }
#pragma unroll
        for (int mi = 0; mi < 4; mi++) {
            int r = wm * 64 + mi * 16 + a_r;
            int c = 2 * kt + a_cc;
            uint32_t addr = base + r * 128 + ((c ^ (r & 7)) << 4);
            LDSM4(af[buf][mi], addr);
        }
    };

    auto consume_stage = [&](uint32_t base) {
        load_frags(0, base, 0);
#pragma unroll
        for (int kt = 0; kt < 4; kt++) {
            const int cb = kt & 1;
            if (kt < 3) load_frags(cb ^ 1, base, kt + 1);
#pragma unroll
            for (int mi = 0; mi < 4; mi++)
#pragma unroll
                for (int ni = 0; ni < 4; ni++)
                    MMA16816(acc[mi][ni], af[cb][mi], bh[cb][ni]);
        }
    };

    for (int kc = 0; kc < NKC - 2; kc++) {
        const int st = kc % NSTAGE;
        __syncthreads();                       // all reads of stage (kc-1)%3 done
        issue_stage(kc + 2, (kc + 2) % NSTAGE);
        CP_WAIT(2);                            // stage kc landed
        __syncthreads();
        consume_stage(sbase + st * STAGE_B);
    }
    // kc = NKC-2: in flight {NKC-2, NKC-1}
    __syncthreads();
    CP_WAIT(1);
    __syncthreads();
    consume_stage(sbase + ((NKC - 2) % NSTAGE) * STAGE_B);
    // kc = NKC-1: in flight {NKC-1}
    __syncthreads();
    CP_WAIT(0);
    __syncthreads();
    consume_stage(sbase + ((NKC - 1) % NSTAGE) * STAGE_B);

    // ---- epilogue: bias + store fp16 (bias hoisted out of mi loop) ----
    const float* bias = which ? bias1 : bias0;
    __half* C = which ? g_h2h : g_i2h;
    const int mrow0 = by * 128 + wm * 64;
    const int ncol0 = bx * 128 + wn * 32;
    float bv0[4], bv1[4];
#pragma unroll
    for (int ni = 0; ni < 4; ni++) {
        const int cc = ncol0 + ni * 8 + (lane & 3) * 2;
        bv0[ni] = __ldg(bias + cc);
        bv1[ni] = __ldg(bias + cc + 1);
    }
#pragma unroll
    for (int mi = 0; mi < 4; mi++) {
        const int r0 = mrow0 + mi * 16 + (lane >> 2);
#pragma unroll
        for (int ni = 0; ni < 4; ni++) {
            const int cc = ncol0 + ni * 8 + (lane & 3) * 2;
            __half2 v0 = __floats2half2_rn(acc[mi][ni][0] + bv0[ni], acc[mi][ni][1] + bv1[ni]);
            __half2 v1 = __floats2half2_rn(acc[mi][ni][2] + bv0[ni], acc[mi][ni][3] + bv1[ni]);
            *reinterpret_cast<__half2*>(C + (size_t)r0 * FH_DIM + cc) = v0;
            *reinterpret_cast<__half2*>(C + (size_t)(r0 + 8) * FH_DIM + cc) = v1;
        }
    }
}

// --------------------------- fused LN/gate epilogue ------------------------
__device__ __forceinline__ float warp_sum(float v) {
#pragma unroll
    for (int o = 16; o; o >>= 1) v += __shfl_down_sync(0xffffffffu, v, o);
    return v;
}
// fast sigmoid/tanh via __expf (rel err ~2^-21, safe at all arguments)
__device__ __forceinline__ float fast_sigmoid(float x) {
    float e = __expf(-x);
    return __fdividef(1.0f, 1.0f + e);
}
__device__ __forceinline__ float fast_tanh(float x) {
    float e = __expf(-2.0f * fabsf(x));
    float r = __fdividef(1.0f - e, 1.0f + e);
    return copysignf(r, x);
}

__global__ __launch_bounds__(256)
void lstm_epilogue(const float* __restrict__ cx,
                   const float* __restrict__ w1, const float* __restrict__ b1,
                   const float* __restrict__ w2, const float* __restrict__ b2,
                   const float* __restrict__ w3, const float* __restrict__ b3,
                   float* __restrict__ hx_new,
                   float* __restrict__ cx_new)
{
    const int r   = blockIdx.x;
    const int tid = threadIdx.x;
    const int lane = tid & 31;
    const int wrp  = tid >> 5;

    const uint4* __restrict__ ri4 =
        reinterpret_cast<const uint4*>(g_i2h + (size_t)r * FH_DIM);
    const uint4* __restrict__ rh4 =
        reinterpret_cast<const uint4*>(g_h2h + (size_t)r * FH_DIM);

    __shared__ __half s_i[FH_DIM];
    __shared__ __half s_h[FH_DIM];
    __shared__ float sc[4][8];
    uint4* s_i4 = reinterpret_cast<uint4*>(s_i);
    uint4* s_h4 = reinterpret_cast<uint4*>(s_h);

    // prefetch cx row + h-position LN params (hidden behind pass-1 reduction)
    float cxv[4], pw1[4], pb1[4], pw2[4], pb2[4], pw3[4], pb3[4];
#pragma unroll
    for (int u = 0; u < 4; u++) {
        const int h = tid + u * 256;
        cxv[u] = cx[(size_t)r * H_DIM + h];
        pw1[u] = w1[h]; pb1[u] = b1[h];
        pw2[u] = w2[h]; pb2[u] = b2[h];
        pw3[u] = w3[h]; pb3[u] = b3[h];
    }

    float s1 = 0.f, q1 = 0.f, s2 = 0.f, q2 = 0.f;
#pragma unroll
    for (int u = 0; u < 2; u++) {
        int j = tid + u * 256;                 // uint4 (8-half) index 0..511
        union { uint4 u4; __half2 h2[4]; } A, Bv;
        A.u4 = ri4[j]; Bv.u4 = rh4[j];
        s_i4[j] = A.u4; s_h4[j] = Bv.u4;
#pragma unroll
        for (int p = 0; p < 4; p++) {
            float2 t = __half22float2(A.h2[p]);
            s1 += t.x + t.y; q1 += t.x * t.x + t.y * t.y;
            t = __half22float2(Bv.h2[p]);
            s2 += t.x + t.y; q2 += t.x * t.x + t.y * t.y;
        }
    }
    s1 = warp_sum(s1); q1 = warp_sum(q1);
    s2 = warp_sum(s2); q2 = warp_sum(q2);
    if (lane == 0) { sc[0][wrp] = s1; sc[1][wrp] = q1; sc[2][wrp] = s2; sc[3][wrp] = q2; }
    __syncthreads();
    if (wrp < 4 && lane < 8) {                 // warp-parallel combine
        float v = sc[wrp][lane];
        v += __shfl_down_sync(0xffu, v, 4);
        v += __shfl_down_sync(0xffu, v, 2);
        v += __shfl_down_sync(0xffu, v, 1);
        if (lane == 0) sc[wrp][0] = v;
    }
    __syncthreads();
    s1 = sc[0][0]; q1 = sc[1][0]; s2 = sc[2][0]; q2 = sc[3][0];

    const float inv_n = 1.0f / (float)FH_DIM;
    const float m1 = s1 * inv_n;
    const float m2 = s2 * inv_n;
    float var1 = fmaxf((q1 - s1 * m1) / (float)(FH_DIM - 1), 0.f);
    float var2 = fmaxf((q2 - s2 * m2) / (float)(FH_DIM - 1), 0.f);
    const float d1 = 1.0f / (sqrtf(var1) + LN_EPS);
    const float d2 = 1.0f / (sqrtf(var2) + LN_EPS);

    float c_reg[4], o_reg[4];
    float s3 = 0.f, q3 = 0.f;
#pragma unroll
    for (int u = 0; u < 4; u++) {
        const int h = tid + u * 256;
        const int jf = h + H_DIM, jo = h + 2 * H_DIM, jc = h + 3 * H_DIM;

        float xi = fmaf((__half2float(s_i[h]) - m1) * d1, pw1[u], pb1[u])
                 + fmaf((__half2float(s_h[h]) - m2) * d2, pw2[u], pb2[u]);
        float xf = fmaf((__half2float(s_i[jf]) - m1) * d1, w1[jf], b1[jf])
                 + fmaf((__half2float(s_h[jf]) - m2) * d2, w2[jf], b2[jf]);
        float xo = fmaf((__half2float(s_i[jo]) - m1) * d1, w1[jo], b1[jo])
                 + fmaf((__half2float(s_h[jo]) - m2) * d2, w2[jo], b2[jo]);
        float xc = fmaf((__half2float(s_i[jc]) - m1) * d1, w1[jc], b1[jc])
                 + fmaf((__half2float(s_h[jc]) - m2) * d2, w2[jc], b2[jc]);

        float ig = fast_sigmoid(xi);
        float fg = fast_sigmoid(xf + FGBIAS);
        float og = fast_sigmoid(xo);
        float ct = fast_tanh(xc);

        float c = fg * cxv[u] + ig * ct;
        c_reg[u] = c;
        o_reg[u] = og;
        s3 += c; q3 += c * c;
        cx_new[(size_t)r * H_DIM + h] = c;
    }

    __syncthreads();
    s3 = warp_sum(s3); q3 = warp_sum(q3);
    if (lane == 0) { sc[0][wrp] = s3; sc[1][wrp] = q3; }
    __syncthreads();
    if (wrp < 2 && lane < 8) {
        float v = sc[wrp][lane];
        v += __shfl_down_sync(0xffu, v, 4);
        v += __shfl_down_sync(0xffu, v, 2);
        v += __shfl_down_sync(0xffu, v, 1);
        if (lane == 0) sc[wrp][0] = v;
    }
    __syncthreads();
    s3 = sc[0][0]; q3 = sc[1][0];

    const float m3 = s3 / (float)H_DIM;
    float var3 = fmaxf((q3 - s3 * m3) / (float)(H_DIM - 1), 0.f);
    const float d3 = 1.0f / (sqrtf(var3) + LN_EPS);

#pragma unroll
    for (int u = 0; u < 4; u++) {
        const int h = tid + u * 256;
        float ln = fmaf((c_reg[u] - m3) * d3, pw3[u], pb3[u]);
        hx_new[(size_t)r * H_DIM + h] = o_reg[u] * fast_tanh(ln);
    }
}

// ------------------------------- launcher ----------------------------------
extern "C" void kernel_launch(void* const* d_in, const int* in_sizes, int n_in,
                              void* d_out, int out_size)
{
    const float* inputs   = (const float*)d_in[0];
    const float* hx       = (const float*)d_in[1];
    const float* cx       = (const float*)d_in[2];
    const float* w_i2h    = (const float*)d_in[3];
    const float* b_i2h    = (const float*)d_in[4];
    const float* w_h2h    = (const float*)d_in[5];
    const float* b_h2h    = (const float*)d_in[6];
    const float* ln_i2h_w = (const float*)d_in[7];
    const float* ln_i2h_b = (const float*)d_in[8];
    const float* ln_h2h_w = (const float*)d_in[9];
    const float* ln_h2h_b = (const float*)d_in[10];
    const float* ln_h2o_w = (const float*)d_in[11];
    const float* ln_h2o_b = (const float*)d_in[12];

    float* out    = (float*)d_out;
    float* hx_new = out;
    float* cx_new = out + (size_t)B_DIM * H_DIM;

    cudaFuncSetAttribute(gemm_tc, cudaFuncAttributeMaxDynamicSharedMemorySize, GEMM_SMEM);

    convert_fp16<<<dim3(2048, 4), 256>>>(inputs, hx, w_i2h, w_h2h);

    gemm_tc<<<dim3(FH_DIM / 128, B_DIM / 128, 2), 256, GEMM_SMEM>>>(b_i2h, b_h2h);

    lstm_epilogue<<<B_DIM, 256>>>(cx,
                                  ln_i2h_w, ln_i2h_b,
                                  ln_h2h_w, ln_h2h_b,
                                  ln_h2o_w, ln_h2o_b,
                                  hx_new, cx_new);
}